// round 5
// baseline (speedup 1.0000x reference)
#include <cuda_runtime.h>
#include <math.h>

#define IM    256
#define MTOT  184320
#define NSP   288
#define NSAM  640
#define ORTHO (1.0f/256.0f)

#define NCHUNK   96
#define M_PER_CH (MTOT/NCHUNK)   // 1920
#define MT       32              // m per adjoint stage
#define NSTAGES  (M_PER_CH/MT)   // 60
#define FWD_M    16              // m per forward block

typedef unsigned long long u64;

// Scratch (static device arrays: allocation-free)
__device__ float2 g_G[MTOT*IM];          // k-space rows expanded over v  (377 MB)
__device__ float2 g_Xp[NCHUNK][IM*IM];   // adjoint partials              (50 MB)

__device__ __forceinline__ float2 cmulf(float2 a, float2 b) {
    return make_float2(a.x*b.x - a.y*b.y, a.x*b.y + a.y*b.x);
}
__device__ __forceinline__ u64 pk(float lo, float hi) {
    u64 r; asm("mov.b64 %0, {%1,%2};" : "=l"(r) : "f"(lo), "f"(hi)); return r;
}
__device__ __forceinline__ float2 unpk(u64 v) {
    float2 f; asm("mov.b64 {%0,%1}, %2;" : "=f"(f.x), "=f"(f.y) : "l"(v)); return f;
}
__device__ __forceinline__ u64 ffma2(u64 a, u64 b, u64 c) {
    u64 d; asm("fma.rn.f32x2 %0, %1, %2, %3;" : "=l"(d) : "l"(a), "l"(b), "l"(c)); return d;
}

// ---------------------------------------------------------------------------
// Forward. Block: 16 m over full 256x256 image. Thread: vg = tid&63 (64 v
// lanes x 4 j, stride 64), mg = tid>>6 (4 groups x 4 m).
// P/Q split packed MAC: P[i][j] += (e.x,e.x)*(c.x,c.y),
//                       Q[i][j] += (e.y,e.y)*(c.x,c.y);  combine at end.
// Phases e^{-i kx (u-128)} staged per 16-u block via direct sincos (one per
// thread), read back as broadcast LDS.64. Single smem image layout.
// ---------------------------------------------------------------------------
__global__ __launch_bounds__(256, 2)
void fwd_kernel(const float2* __restrict__ img,
                const float2* __restrict__ yrad,
                const float*  __restrict__ lamp,
                const float*  __restrict__ kxs,
                const float*  __restrict__ kys)
{
    extern __shared__ u64 smf[];
    u64*    imgA = smf;               // 16 u x 256 v = 4096
    u64*    EsXX = smf + 4096;        // 16 m x 16 u  = 256
    u64*    EsYY = smf + 4352;        // 256
    float2* red  = (float2*)(smf + 4608);  // 8 warps x 4 i

    const int tid = threadIdx.x;
    const int vg  = tid & 63;
    const int mg  = tid >> 6;
    const int wid = tid >> 5;
    const int m0  = blockIdx.x * FWD_M;

    // phase staging constants for this thread's (mm, uu) slot
    const int   smm = tid >> 4;
    const int   suu = tid & 15;
    const float skx = kxs[m0 + smm];

    u64 P[4][4], Q[4][4];
#pragma unroll
    for (int i = 0; i < 4; i++)
#pragma unroll
        for (int j = 0; j < 4; j++) { P[i][j] = 0ull; Q[i][j] = 0ull; }

    for (int ub = 0; ub < IM; ub += 16) {
        __syncthreads();
        // stage image tile (single layout)
#pragma unroll
        for (int r = 0; r < 16; r++) {
            int idx = r * 256 + tid;
            float2 c = img[(ub + (idx >> 8)) * IM + (idx & 255)];
            imgA[idx] = pk(c.x, c.y);
        }
        // stage phase tile: e = e^{-i kx (ub+uu-128)} (direct sincos)
        {
            float s, c;
            sincosf(skx * (float)(ub + suu - 128), &s, &c);
            EsXX[tid] = pk(c, c);
            EsYY[tid] = pk(-s, -s);
        }
        __syncthreads();

#pragma unroll
        for (int uu = 0; uu < 16; uu++) {
            u64 ca[4];
#pragma unroll
            for (int j = 0; j < 4; j++) ca[j] = imgA[uu * 256 + vg + 64 * j];
#pragma unroll
            for (int i = 0; i < 4; i++) {
                const int eidx = (mg * 4 + i) * 16 + uu;
                u64 exx = EsXX[eidx];
                u64 eyy = EsYY[eidx];
#pragma unroll
                for (int j = 0; j < 4; j++) {
                    P[i][j] = ffma2(exx, ca[j], P[i][j]);
                    Q[i][j] = ffma2(eyy, ca[j], Q[i][j]);
                }
            }
        }
    }

    const float lam = 1.0f / (1.0f + expf(-lamp[0]));
    const float vgc = (float)(vg - 128);

    // pass 1: Ey-weighted partial sums, warp-reduce, stash per-warp sums
#pragma unroll
    for (int i = 0; i < 4; i++) {
        const int m = m0 + mg * 4 + i;
        const float kyv = kys[m];
        float s, c;
        sincosf(kyv * vgc, &s, &c);
        float2 e = make_float2(c, -s);              // e^{-i ky (vg-128)}
        sincosf(kyv * 64.0f, &s, &c);
        const float2 eys = make_float2(c, -s);      // e^{-i 64 ky}

        float2 t = make_float2(0.f, 0.f);
#pragma unroll
        for (int j = 0; j < 4; j++) {
            float2 Pj = unpk(P[i][j]);
            float2 Qj = unpk(Q[i][j]);
            float2 a  = make_float2(Pj.x - Qj.y, Pj.y + Qj.x);   // T[m, v_j]
            t.x = fmaf(a.x, e.x, fmaf(-a.y, e.y, t.x));
            t.y = fmaf(a.x, e.y, fmaf( a.y, e.x, t.y));
            e = cmulf(e, eys);
        }
#pragma unroll
        for (int o = 16; o > 0; o >>= 1) {
            t.x += __shfl_xor_sync(0xffffffffu, t.x, o);
            t.y += __shfl_xor_sync(0xffffffffu, t.y, o);
        }
        if ((tid & 31) == 0) red[wid * 4 + i] = t;
    }
    __syncthreads();

    // pass 2: combine warp pair, blend, expand G row
#pragma unroll
    for (int i = 0; i < 4; i++) {
        const int m = m0 + mg * 4 + i;
        float2 ta = red[(2 * mg    ) * 4 + i];
        float2 tb = red[(2 * mg + 1) * 4 + i];
        float2 t  = make_float2(ta.x + tb.x, ta.y + tb.y);

        const float kxv = kxs[m];
        const float kyv = kys[m];
        const float dcf = sqrtf(kxv * kxv + kyv * kyv);
        const int   sp  = m / NSAM;
        const int   sam = m - sp * NSAM;
        const float2 y  = yrad[sam * NSP + sp];
        const float  w  = lam * dcf * ORTHO;
        const float2 k  = make_float2(fmaf(w, t.x, (1.0f - lam) * y.x),
                                      fmaf(w, t.y, (1.0f - lam) * y.y));

        // G[m, v] = k * e^{+i ky (v-128)}, v = vg + 64 j
        float s, c;
        sincosf(kyv * vgc, &s, &c);
        float2 cur = make_float2(c, s);             // e^{+i ky (vg-128)}
        sincosf(kyv * 64.0f, &s, &c);
        const float2 esp = make_float2(c, s);       // e^{+i 64 ky}
#pragma unroll
        for (int j = 0; j < 4; j++) {
            g_G[m * IM + vg + 64 * j] = cmulf(k, cur);
            cur = cmulf(cur, esp);
        }
    }
}

// ---------------------------------------------------------------------------
// Adjoint: X[u,v] = sum_m e^{+i kx_m (u-128)} * G[m,v].
// Block = (u-tile 32, v-tile 128, chunk) — chunk slowest so the 16 blocks
// sharing one chunk's G slice are launch-adjacent (L2 reuse).
// Thread: ug = tid>>5 (warp, 4 u each), vg = tid&31 (4 v, stride 32).
// P/Q split, single G layout, phases staged via short recurrence.
// ---------------------------------------------------------------------------
__global__ __launch_bounds__(256, 2)
void adj_kernel(const float* __restrict__ kxs)
{
    extern __shared__ u64 sma[];
    u64* EsXX = sma;                  // 32 m x 32 u = 1024
    u64* EsYY = sma + 1024;
    u64* Gs   = sma + 2048;           // 32 m x 128 v = 4096

    const int tid   = threadIdx.x;
    const int vg    = tid & 31;
    const int ug    = tid >> 5;
    const int u0    = blockIdx.x * 32;
    const int v0    = blockIdx.y * 128;
    const int chunk = blockIdx.z;
    const int mbase = chunk * M_PER_CH;

    // staging slot for phases: mm = tid>>3, 4 u's starting at (tid&7)*4
    const int smm = tid >> 3;
    const int su0 = (tid & 7) * 4;

    u64 P[4][4], Q[4][4];
#pragma unroll
    for (int i = 0; i < 4; i++)
#pragma unroll
        for (int j = 0; j < 4; j++) { P[i][j] = 0ull; Q[i][j] = 0ull; }

    for (int st = 0; st < NSTAGES; st++) {
        const int ms0 = mbase + st * MT;
        __syncthreads();
        // stage G tile (single layout): 32 m x 128 v
#pragma unroll
        for (int r = 0; r < 16; r++) {
            int idx = r * 256 + tid;
            float2 g = g_G[(ms0 + (idx >> 7)) * IM + v0 + (idx & 127)];
            Gs[idx] = pk(g.x, g.y);
        }
        // stage phase tile: e^{+i kx (u-128)}, 4 u per thread via recurrence
        {
            const float kxv = kxs[ms0 + smm];
            float s, c;
            sincosf(kxv * (float)(u0 + su0 - 128), &s, &c);
            float2 cur = make_float2(c, s);
            sincosf(kxv, &s, &c);
            const float2 stp = make_float2(c, s);
#pragma unroll
            for (int q = 0; q < 4; q++) {
                EsXX[smm * 32 + su0 + q] = pk(cur.x, cur.x);
                EsYY[smm * 32 + su0 + q] = pk(cur.y, cur.y);
                cur = cmulf(cur, stp);
            }
        }
        __syncthreads();

#pragma unroll 2
        for (int mm = 0; mm < MT; mm++) {
            u64 gv[4];
#pragma unroll
            for (int j = 0; j < 4; j++) gv[j] = Gs[mm * 128 + vg + 32 * j];
#pragma unroll
            for (int i = 0; i < 4; i++) {
                u64 exx = EsXX[mm * 32 + ug * 4 + i];
                u64 eyy = EsYY[mm * 32 + ug * 4 + i];
#pragma unroll
                for (int j = 0; j < 4; j++) {
                    P[i][j] = ffma2(exx, gv[j], P[i][j]);
                    Q[i][j] = ffma2(eyy, gv[j], Q[i][j]);
                }
            }
        }
    }

#pragma unroll
    for (int i = 0; i < 4; i++) {
        const int u = u0 + ug * 4 + i;
#pragma unroll
        for (int j = 0; j < 4; j++) {
            const int v = v0 + vg + 32 * j;
            float2 Pj = unpk(P[i][j]);
            float2 Qj = unpk(Q[i][j]);
            g_Xp[chunk][u * IM + v] = make_float2(Pj.x - Qj.y, Pj.y + Qj.x);
        }
    }
}

// ---------------------------------------------------------------------------
// Reduce partials, scale, write (H,W,2) interleaved output.
// ---------------------------------------------------------------------------
__global__ __launch_bounds__(256)
void reduce_kernel(float* __restrict__ out)
{
    const int i = blockIdx.x * 256 + threadIdx.x;
    float sx = 0.f, sy = 0.f;
#pragma unroll 8
    for (int c = 0; c < NCHUNK; c++) {
        float2 p = g_Xp[c][i];
        sx += p.x; sy += p.y;
    }
    out[2*i + 0] = sx * ORTHO;
    out[2*i + 1] = sy * ORTHO;
}

// ---------------------------------------------------------------------------
extern "C" void kernel_launch(void* const* d_in, const int* in_sizes, int n_in,
                              void* d_out, int out_size)
{
    const float2* img  = (const float2*)d_in[0];
    const float2* yrad = (const float2*)d_in[1];
    const float*  lamp = (const float*)d_in[2];
    const float*  ktr  = (const float*)d_in[3];
    const float*  kxs  = ktr;
    const float*  kys  = ktr + MTOT;
    float* out = (float*)d_out;

    const int FWD_SMEM = 4608 * (int)sizeof(u64) + 32 * (int)sizeof(float2); // ~37 KB
    const int ADJ_SMEM = 6144 * (int)sizeof(u64);                            // 48 KB
    cudaFuncSetAttribute(fwd_kernel, cudaFuncAttributeMaxDynamicSharedMemorySize, FWD_SMEM);
    cudaFuncSetAttribute(adj_kernel, cudaFuncAttributeMaxDynamicSharedMemorySize, ADJ_SMEM);

    fwd_kernel<<<MTOT/FWD_M, 256, FWD_SMEM>>>(img, yrad, lamp, kxs, kys);

    dim3 agrid(IM/32, IM/128, NCHUNK);   // chunk slowest -> L2 reuse of G slice
    adj_kernel<<<agrid, 256, ADJ_SMEM>>>(kxs);

    reduce_kernel<<<IM*IM/256, 256>>>(out);
}

// round 8
// speedup vs baseline: 3.6742x; 3.6742x over previous
#include <cuda_runtime.h>
#include <math.h>
#include <stdint.h>

#define IM     256
#define MTOT   184320
#define ORTHO  (1.0f/256.0f)
#define NSPLIT 72
#define ADJ_MPER (MTOT/NSPLIT)   // 2560 m per split
#define ADJ_ST   (ADJ_MPER/16)   // 160 stages (16 m = 32 k per stage)

// ---------------- static scratch (allocation-free) -------------------------
__device__ float  g_Bf[512*512];                    // fwd B operand (1 MB)
__device__ float2 g_S1x[MTOT], g_S16x[MTOT], g_T0x[MTOT];
__device__ float2 g_S1y[MTOT], g_S16y[MTOT], g_S64y[MTOT], g_S128y[MTOT];
__device__ float2 g_E0[MTOT];                       // kdc * e^{-i 128 ky}
__device__ float  g_P[(size_t)8*NSPLIT*128*128];    // adjoint partials (37.7 MB)

// ---------------- helpers --------------------------------------------------
__device__ __forceinline__ float2 cmulf(float2 a, float2 b) {
    return make_float2(a.x*b.x - a.y*b.y, a.x*b.y + a.y*b.x);
}
__device__ __forceinline__ float2 conjf(float2 a) { return make_float2(a.x, -a.y); }
// cvt.rna.tf32.f32 requires a .b32 destination register
__device__ __forceinline__ uint32_t tf32u(float x) {
    uint32_t r; asm("cvt.rna.tf32.f32 %0, %1;" : "=r"(r) : "f"(x)); return r;
}
__device__ __forceinline__ float tf32f(float x) {
    uint32_t r; asm("cvt.rna.tf32.f32 %0, %1;" : "=r"(r) : "f"(x));
    return __uint_as_float(r);
}
// b^e for e in 0..15 (4-bit square-and-multiply)
__device__ __forceinline__ float2 cpow4(float2 b, int e) {
    float2 r = make_float2(1.f, 0.f);
#pragma unroll
    for (int i = 0; i < 4; i++) { if (e & (1 << i)) r = cmulf(r, b); b = cmulf(b, b); }
    return r;
}
__device__ __forceinline__ void mma8(float* d, const uint32_t* a, const uint32_t* b) {
    asm volatile(
        "mma.sync.aligned.m16n8k8.row.col.f32.tf32.tf32.f32 "
        "{%0,%1,%2,%3}, {%4,%5,%6,%7}, {%8,%9}, {%0,%1,%2,%3};"
        : "+f"(d[0]), "+f"(d[1]), "+f"(d[2]), "+f"(d[3])
        : "r"(a[0]), "r"(a[1]), "r"(a[2]), "r"(a[3]), "r"(b[0]), "r"(b[1]));
}

// ---------------- prep: per-m phase-step tables ----------------------------
__global__ __launch_bounds__(256) void prep_tab(const float* __restrict__ kxs,
                                                const float* __restrict__ kys)
{
    int m = blockIdx.x * 256 + threadIdx.x;
    float s, c;
    float kx = kxs[m], ky = kys[m];
    sincosf(kx, &s, &c);
    float2 S1 = make_float2(c, s);                       // e^{+i kx}
    float2 S2 = cmulf(S1, S1), S4 = cmulf(S2, S2), S8 = cmulf(S4, S4);
    float2 S16 = cmulf(S8, S8), S32 = cmulf(S16, S16), S64 = cmulf(S32, S32);
    float2 S128 = cmulf(S64, S64);
    g_S1x[m] = S1; g_S16x[m] = S16; g_T0x[m] = conjf(S128);   // e^{-i 128 kx}
    sincosf(ky, &s, &c);
    S1 = make_float2(c, s);                              // e^{+i ky}
    S2 = cmulf(S1, S1); S4 = cmulf(S2, S2); S8 = cmulf(S4, S4);
    S16 = cmulf(S8, S8); S32 = cmulf(S16, S16); S64 = cmulf(S32, S32);
    S128 = cmulf(S64, S64);
    g_S1y[m] = S1; g_S16y[m] = S16; g_S64y[m] = S64; g_S128y[m] = S128;
}

// B_f[k][n] (tf32-rounded): n<256 (v=n): k<256 -> R[k][v], else -I[k-256][v]
//                           n>=256:     k<256 -> I[k][v],  else  R[k-256][v]
__global__ __launch_bounds__(256) void prep_bf(const float2* __restrict__ img)
{
    int idx = blockIdx.x * 256 + threadIdx.x;
    int k = idx >> 9, n = idx & 511;
    int v = n & 255, u = k & 255;
    float2 g = img[u * 256 + v];
    float val = (n < 256) ? ((k < 256) ? g.x : -g.y)
                          : ((k < 256) ? g.y :  g.x);
    g_Bf[idx] = tf32f(val);
}

// ---------------------------------------------------------------------------
// Forward: per CTA 128 m. T[m, n=512] = A[m,k=512] @ B[k,n], A = [cos | -sin]
// phases generated in smem from tables. Fused epilogue: Ey-weighted v-reduce,
// sigmoid blend, write E0[m] = kdc * e^{-i 128 ky}. No G materialization.
// Warp layout: 8 warps = 4 m-groups (32 m) x 2 n-groups (64 n per nt-tile).
// ---------------------------------------------------------------------------
__global__ __launch_bounds__(256, 2)
void fwd_gemm(const float2* __restrict__ yrad, const float* __restrict__ lamp,
              const float* __restrict__ kxs, const float* __restrict__ kys)
{
    __shared__ uint32_t As[128 * 36];
    __shared__ uint32_t Bs[32 * 136];
    __shared__ float2 t_acc[2][128];

    const int tid = threadIdx.x, lane = tid & 31, wid = tid >> 5;
    const int wm = wid >> 1, wn = wid & 1;
    const int m0 = blockIdx.x * 128;

    // A-generation constants (thread owns row gr, half gh: 16 consecutive k)
    const int gr = tid >> 1, gh = tid & 1;
    const float2 gT0  = g_T0x[m0 + gr];
    const float2 gS16 = g_S16x[m0 + gr];
    const float2 gS1c = conjf(g_S1x[m0 + gr]);

    t_acc[tid >> 7][tid & 127] = make_float2(0.f, 0.f);
    __syncthreads();

    for (int nt = 0; nt < 4; nt++) {
        float acc[2][8][4];
#pragma unroll
        for (int i = 0; i < 2; i++)
#pragma unroll
            for (int j = 0; j < 8; j++)
#pragma unroll
                for (int q = 0; q < 4; q++) acc[i][j][q] = 0.f;

        for (int ch = 0; ch < 16; ch++) {
            const int k0 = ch * 32;
            __syncthreads();
            // A chunk: A[m][k] = (k<256 ? cos : -sin)(kx*(u-128)), u = k&255.
            // cur = e^{-i kx (uu-128)} = conj(T0x * S16x^{uu/16}), step conj(S1x)
            {
                int uu = (k0 + 16 * gh) & 255;
                float2 cur = conjf(cmulf(gT0, cpow4(gS16, uu >> 4)));
                const int rb = gr * 36 + 16 * gh;
                const bool iscos = (k0 < 256);
#pragma unroll
                for (int q = 0; q < 16; q++) {
                    As[rb + q] = tf32u(iscos ? cur.x : cur.y);   // cur.y = -sin
                    cur = cmulf(cur, gS1c);
                }
            }
            // B chunk: 32 k x 128 n from g_Bf (pre-rounded)
#pragma unroll
            for (int it = 0; it < 4; it++) {
                int idx = it * 256 + tid;
                int r = idx >> 5, c4 = idx & 31;
                uint4 v = *(const uint4*)&g_Bf[(size_t)(k0 + r) * 512 + nt * 128 + c4 * 4];
                *(uint4*)&Bs[r * 136 + c4 * 4] = v;
            }
            __syncthreads();
            // MMA: 4 k-steps x (2 m-frags x 8 n-frags)
#pragma unroll
            for (int ks = 0; ks < 4; ks++) {
                const int kk = ks * 8;
                uint32_t af[2][4];
#pragma unroll
                for (int fm = 0; fm < 2; fm++) {
                    int r = wm * 32 + fm * 16 + (lane >> 2);
                    int cb = kk + (lane & 3);
                    af[fm][0] = As[r * 36 + cb];
                    af[fm][1] = As[(r + 8) * 36 + cb];
                    af[fm][2] = As[r * 36 + cb + 4];
                    af[fm][3] = As[(r + 8) * 36 + cb + 4];
                }
#pragma unroll
                for (int fn = 0; fn < 8; fn++) {
                    int br = kk + (lane & 3);
                    int bc = wn * 64 + fn * 8 + (lane >> 2);
                    uint32_t bf[2];
                    bf[0] = Bs[br * 136 + bc];
                    bf[1] = Bs[(br + 4) * 136 + bc];
                    mma8(acc[0][fn], af[0], bf);
                    mma8(acc[1][fn], af[1], bf);
                }
            }
        }
        // fused partial reduction over this nt's 128 n columns
        // p(v) = e^{-i ky (v-128)} = S128y * conj(S1y)^v
#pragma unroll
        for (int fm = 0; fm < 2; fm++)
#pragma unroll
        for (int cp = 0; cp < 2; cp++) {
            const int rl = wm * 32 + fm * 16 + cp * 8 + (lane >> 2);
            const int m = m0 + rl;
            const float2 S1c  = conjf(g_S1y[m]);
            const float2 S64c = conjf(g_S64y[m]);
            const float2 EYp  = g_S128y[m];
            const int a2 = ((nt & 1) << 1) | wn;          // vbase = 64*a2
            float2 S2c = cmulf(S1c, S1c);
            float2 base = cmulf(cmulf(EYp, cpow4(S64c, a2)), cpow4(S2c, lane & 3));
            float2 S8c = cmulf(S2c, S2c); S8c = cmulf(S8c, S8c);
            float2 pb = base;
            float tx = 0.f, ty = 0.f;
#pragma unroll
            for (int fn = 0; fn < 8; fn++) {
                float v0 = acc[fm][fn][cp * 2 + 0];
                float v1 = acc[fm][fn][cp * 2 + 1];
                float2 p1 = cmulf(pb, S1c);
                if (nt < 2) { tx += v0 * pb.x + v1 * p1.x;  ty += v0 * pb.y + v1 * p1.y; }
                else        { tx -= v0 * pb.y + v1 * p1.y;  ty += v0 * pb.x + v1 * p1.x; }
                pb = cmulf(pb, S8c);
            }
            tx += __shfl_xor_sync(0xffffffffu, tx, 1);
            ty += __shfl_xor_sync(0xffffffffu, ty, 1);
            tx += __shfl_xor_sync(0xffffffffu, tx, 2);
            ty += __shfl_xor_sync(0xffffffffu, ty, 2);
            if ((lane & 3) == 0) {                         // unique (wn, rl) owner
                t_acc[wn][rl].x += tx;
                t_acc[wn][rl].y += ty;
            }
        }
    }
    __syncthreads();
    if (tid < 128) {
        const int m = m0 + tid;
        float2 t = make_float2(t_acc[0][tid].x + t_acc[1][tid].x,
                               t_acc[0][tid].y + t_acc[1][tid].y);
        const float lam = 1.0f / (1.0f + expf(-lamp[0]));
        const float kx = kxs[m], ky = kys[m];
        const float dcf = sqrtf(kx * kx + ky * ky);
        const int sp = m / 640, sam = m - sp * 640;
        const float2 y = yrad[sam * 288 + sp];
        const float w = lam * dcf * ORTHO;
        float2 kdc = make_float2(fmaf(w, t.x, (1.f - lam) * y.x),
                                 fmaf(w, t.y, (1.f - lam) * y.y));
        g_E0[m] = cmulf(kdc, conjf(g_S128y[m]));          // kdc * e^{-i 128 ky}
    }
}

// ---------------------------------------------------------------------------
// Adjoint: X[u, n=512] = A[u, k=2M] @ B[n, k]^T with pair-interleaved K:
//   A[u][2m+0]=cos(kx u'), A[u][2m+1]=sin(kx u'),  u' = ut*128 + u - 128
//   Re cols (nt<2): B[2m][v]=Gr, B[2m+1][v]=-Gi;  Im: B[2m][v]=Gi, B[2m+1][v]=Gr
//   G(v) = E0[m] * S1y^v regenerated per stage (no G in DRAM).
// grid = (split 72, ut 2, nt 4); per CTA K-slice = 2560 m = 160 stages.
// ---------------------------------------------------------------------------
__global__ __launch_bounds__(256, 2)
void adj_gemm()
{
    __shared__ uint32_t As[128 * 36];
    __shared__ uint32_t Bs[32 * 136];

    const int tid = threadIdx.x, lane = tid & 31, wid = tid >> 5;
    const int wm = wid >> 1, wn = wid & 1;
    const int split = blockIdx.x, ut = blockIdx.y, nt = blockIdx.z;
    const int mb = split * ADJ_MPER;
    const int gm = tid >> 4, gs = tid & 15;

    float acc[2][8][4];
#pragma unroll
    for (int i = 0; i < 2; i++)
#pragma unroll
        for (int j = 0; j < 8; j++)
#pragma unroll
            for (int q = 0; q < 4; q++) acc[i][j][q] = 0.f;

    for (int st = 0; st < ADJ_ST; st++) {
        const int ms0 = mb + st * 16;
        __syncthreads();
        // A tile: u walk stride 16 (step S16x); base = (ut? 1 : T0x) * S1x^gs
        {
            const int m = ms0 + gm;
            float2 cur = cpow4(g_S1x[m], gs);
            if (ut == 0) cur = cmulf(g_T0x[m], cur);
            const float2 stp = g_S16x[m];
#pragma unroll
            for (int q = 0; q < 8; q++) {
                const int u = gs + 16 * q;
                As[u * 36 + 2 * gm]     = tf32u(cur.x);   // cos
                As[u * 36 + 2 * gm + 1] = tf32u(cur.y);   // sin
                cur = cmulf(cur, stp);
            }
        }
        // B tile: v walk stride 16 (step S16y); base = E0 * S128y^{nt&1} * S1y^gs
        {
            const int m = ms0 + gm;
            float2 cur = cmulf(g_E0[m], cpow4(g_S1y[m], gs));
            if (nt & 1) cur = cmulf(cur, g_S128y[m]);
            const float2 stp = g_S16y[m];
#pragma unroll
            for (int q = 0; q < 8; q++) {
                const int v = gs + 16 * q;
                if (nt < 2) {
                    Bs[(2 * gm)     * 136 + v] = tf32u(cur.x);
                    Bs[(2 * gm + 1) * 136 + v] = tf32u(-cur.y);
                } else {
                    Bs[(2 * gm)     * 136 + v] = tf32u(cur.y);
                    Bs[(2 * gm + 1) * 136 + v] = tf32u(cur.x);
                }
                cur = cmulf(cur, stp);
            }
        }
        __syncthreads();
#pragma unroll
        for (int ks = 0; ks < 4; ks++) {
            const int kk = ks * 8;
            uint32_t af[2][4];
#pragma unroll
            for (int fm = 0; fm < 2; fm++) {
                int r = wm * 32 + fm * 16 + (lane >> 2);
                int cb = kk + (lane & 3);
                af[fm][0] = As[r * 36 + cb];
                af[fm][1] = As[(r + 8) * 36 + cb];
                af[fm][2] = As[r * 36 + cb + 4];
                af[fm][3] = As[(r + 8) * 36 + cb + 4];
            }
#pragma unroll
            for (int fn = 0; fn < 8; fn++) {
                int br = kk + (lane & 3);
                int bc = wn * 64 + fn * 8 + (lane >> 2);
                uint32_t bf[2];
                bf[0] = Bs[br * 136 + bc];
                bf[1] = Bs[(br + 4) * 136 + bc];
                mma8(acc[0][fn], af[0], bf);
                mma8(acc[1][fn], af[1], bf);
            }
        }
    }
    float* outp = g_P + (size_t)((ut * 4 + nt) * NSPLIT + split) * 16384;
#pragma unroll
    for (int fm = 0; fm < 2; fm++)
#pragma unroll
    for (int cp = 0; cp < 2; cp++) {
        const int u = wm * 32 + fm * 16 + cp * 8 + (lane >> 2);
#pragma unroll
        for (int fn = 0; fn < 8; fn++) {
            const int n = wn * 64 + fn * 8 + 2 * (lane & 3);
            *(float2*)&outp[u * 128 + n] =
                make_float2(acc[fm][fn][cp * 2], acc[fm][fn][cp * 2 + 1]);
        }
    }
}

// ---------------------------------------------------------------------------
__global__ __launch_bounds__(256) void reduce_k(float* __restrict__ out)
{
    const int idx = blockIdx.x * 256 + threadIdx.x;     // 0..131071
    const int ug = idx >> 9, ng = idx & 511;
    const int ut = ug >> 7, ul = ug & 127, nt = ng >> 7, nl = ng & 127;
    const float* p = g_P + (size_t)((ut * 4 + nt) * NSPLIT) * 16384 + ul * 128 + nl;
    float s = 0.f;
#pragma unroll 8
    for (int sp = 0; sp < NSPLIT; sp++) s += p[(size_t)sp * 16384];
    const int v = ng & 255, c = ng >> 8;
    out[(ug * 256 + v) * 2 + c] = s * ORTHO;
}

// ---------------------------------------------------------------------------
extern "C" void kernel_launch(void* const* d_in, const int* in_sizes, int n_in,
                              void* d_out, int out_size)
{
    const float2* img  = (const float2*)d_in[0];
    const float2* yrad = (const float2*)d_in[1];
    const float*  lamp = (const float*)d_in[2];
    const float*  ktr  = (const float*)d_in[3];
    const float*  kxs  = ktr;
    const float*  kys  = ktr + MTOT;
    float* out = (float*)d_out;

    prep_tab<<<MTOT/256, 256>>>(kxs, kys);
    prep_bf<<<1024, 256>>>(img);
    fwd_gemm<<<MTOT/128, 256>>>(yrad, lamp, kxs, kys);
    adj_gemm<<<dim3(NSPLIT, 2, 4), 256>>>();
    reduce_k<<<512, 256>>>(out);
}

// round 9
// speedup vs baseline: 4.0503x; 1.1024x over previous
#include <cuda_runtime.h>
#include <math.h>
#include <stdint.h>

#define IM     256
#define MTOT   184320
#define ORTHO  (1.0f/256.0f)
#define NSPLIT 72
#define ADJ_MPER (MTOT/NSPLIT)   // 2560 m per split
#define ADJ_ST   (ADJ_MPER/16)   // 160 stages (16 m = 32 k per stage)

// ---------------- static scratch (allocation-free) -------------------------
__device__ float  g_Bf[512*512];                    // fwd B operand (1 MB)
__device__ float2 g_S1x[MTOT], g_S8x[MTOT];
__device__ float2 g_S1y[MTOT], g_S8y[MTOT], g_S64y[MTOT], g_S128y[MTOT];
__device__ float2 g_PCH[(size_t)MTOT*16];   // conj(T0x * S16x^j), j 0..15 (fwd A base)
__device__ float2 g_PXU[(size_t)MTOT*16];   // [ut=0]: T0x*S1x^s ; [ut=1]: S1x^s
__device__ float2 g_PYB[(size_t)MTOT*16];   // [b=0]: S1y^s ; [b=1]: S128y*S1y^s
__device__ float2 g_E0[MTOT];               // kdc * e^{-i 128 ky}
__device__ float  g_P[(size_t)8*NSPLIT*128*128];    // adjoint partials (37.7 MB)

// ---------------- helpers --------------------------------------------------
__device__ __forceinline__ float2 cmulf(float2 a, float2 b) {
    return make_float2(a.x*b.x - a.y*b.y, a.x*b.y + a.y*b.x);
}
__device__ __forceinline__ float2 conjf(float2 a) { return make_float2(a.x, -a.y); }
__device__ __forceinline__ uint32_t tf32u(float x) {
    uint32_t r; asm("cvt.rna.tf32.f32 %0, %1;" : "=r"(r) : "f"(x)); return r;
}
__device__ __forceinline__ float tf32f(float x) {
    uint32_t r; asm("cvt.rna.tf32.f32 %0, %1;" : "=r"(r) : "f"(x));
    return __uint_as_float(r);
}
__device__ __forceinline__ float2 cpow4(float2 b, int e) {
    float2 r = make_float2(1.f, 0.f);
#pragma unroll
    for (int i = 0; i < 4; i++) { if (e & (1 << i)) r = cmulf(r, b); b = cmulf(b, b); }
    return r;
}
__device__ __forceinline__ void mma8(float* d, const uint32_t* a, const uint32_t* b) {
    asm volatile(
        "mma.sync.aligned.m16n8k8.row.col.f32.tf32.tf32.f32 "
        "{%0,%1,%2,%3}, {%4,%5,%6,%7}, {%8,%9}, {%0,%1,%2,%3};"
        : "+f"(d[0]), "+f"(d[1]), "+f"(d[2]), "+f"(d[3])
        : "r"(a[0]), "r"(a[1]), "r"(a[2]), "r"(a[3]), "r"(b[0]), "r"(b[1]));
}
__device__ __forceinline__ uint32_t su32(const void* p) {
    uint32_t a; asm("{ .reg .u64 t; cvta.to.shared.u64 t, %1; cvt.u32.u64 %0, t; }" : "=r"(a) : "l"(p));
    return a;
}
__device__ __forceinline__ void cp16(uint32_t saddr, const void* g) {
    asm volatile("cp.async.cg.shared.global [%0], [%1], 16;" :: "r"(saddr), "l"(g));
}

// ---------------- prep: per-m phase/power tables ---------------------------
__global__ __launch_bounds__(256) void prep_tab(const float* __restrict__ kxs,
                                                const float* __restrict__ kys)
{
    int m = blockIdx.x * 256 + threadIdx.x;
    float s, c;
    float kx = kxs[m], ky = kys[m];
    sincosf(kx, &s, &c);
    float2 S1 = make_float2(c, s);
    float2 S2 = cmulf(S1,S1), S4 = cmulf(S2,S2), S8 = cmulf(S4,S4);
    float2 S16 = cmulf(S8,S8), S32 = cmulf(S16,S16), S64 = cmulf(S32,S32);
    float2 S128 = cmulf(S64,S64);
    float2 T0 = conjf(S128);                         // e^{-i 128 kx}
    g_S1x[m] = S1; g_S8x[m] = S8;
    float2 q = T0;
#pragma unroll
    for (int j = 0; j < 16; j++) { g_PCH[(size_t)m*16 + j] = conjf(q); q = cmulf(q, S16); }
    float2 p = make_float2(1.f, 0.f);
#pragma unroll
    for (int s8 = 0; s8 < 8; s8++) {
        g_PXU[(size_t)m*16 + s8]     = cmulf(T0, p);   // ut=0
        g_PXU[(size_t)m*16 + 8 + s8] = p;              // ut=1
        p = cmulf(p, S1);
    }
    sincosf(ky, &s, &c);
    S1 = make_float2(c, s);
    S2 = cmulf(S1,S1); S4 = cmulf(S2,S2); S8 = cmulf(S4,S4);
    S16 = cmulf(S8,S8); S32 = cmulf(S16,S16); S64 = cmulf(S32,S32);
    S128 = cmulf(S64,S64);
    g_S1y[m] = S1; g_S8y[m] = S8; g_S64y[m] = S64; g_S128y[m] = S128;
    p = make_float2(1.f, 0.f);
#pragma unroll
    for (int s8 = 0; s8 < 8; s8++) {
        g_PYB[(size_t)m*16 + s8]     = p;
        g_PYB[(size_t)m*16 + 8 + s8] = cmulf(S128, p);
        p = cmulf(p, S1);
    }
}

// B_f[k][n]: n<256 (v=n): k<256 -> R[k][v], else -I[k-256][v]
//            n>=256:      k<256 -> I[k][v], else  R[k-256][v]
__global__ __launch_bounds__(256) void prep_bf(const float2* __restrict__ img)
{
    int idx = blockIdx.x * 256 + threadIdx.x;
    int k = idx >> 9, n = idx & 511;
    int v = n & 255, u = k & 255;
    float2 g = img[u * 256 + v];
    float val = (n < 256) ? ((k < 256) ? g.x : -g.y)
                          : ((k < 256) ? g.y :  g.x);
    g_Bf[idx] = tf32f(val);
}

// ---------------------------------------------------------------------------
// Forward GEMM. CTA: 128 m, 128 threads (4 warps, 2 wm x 2 wn), warp 64x64.
// nt loop over 4 n-quarters of N=512. A generated in smem from PCH tables
// (prefetched 1 stage ahead); B staged via cp.async double buffer.
// Fused Ey-reduce + blend epilogue -> g_E0.
// ---------------------------------------------------------------------------
__global__ __launch_bounds__(128)
void fwd_gemm(const float2* __restrict__ yrad, const float* __restrict__ lamp,
              const float* __restrict__ kxs, const float* __restrict__ kys)
{
    extern __shared__ uint32_t sh[];
    uint32_t* As = sh;                       // 128*36 = 4608
    uint32_t* Bs = sh + 4608;                // 2 * (32*136) = 8704
    float2*   t_acc = (float2*)(sh + 4608 + 8704);  // [2][128]

    const int tid = threadIdx.x, lane = tid & 31, wid = tid >> 5;
    const int wm = wid >> 1, wn = wid & 1;
    const int m0 = blockIdx.x * 128;
    const int gh = tid & 1, grow = tid >> 1;          // A-gen: rows grow, grow+64

    const float2 S1c0 = conjf(g_S1x[m0 + grow]);
    const float2 S1c1 = conjf(g_S1x[m0 + grow + 64]);

    t_acc[tid]       = make_float2(0.f, 0.f);
    t_acc[128 + tid] = make_float2(0.f, 0.f);

    // prefetch stage ls=0: A bases + B tile into buf 0
    float2 bA0 = g_PCH[(size_t)(m0 + grow)      * 16 + gh];
    float2 bA1 = g_PCH[(size_t)(m0 + grow + 64) * 16 + gh];
    {
        const uint32_t sb = su32(Bs);
#pragma unroll
        for (int it = 0; it < 8; it++) {
            int idx = it * 128 + tid, r = idx >> 5, c4 = idx & 31;
            cp16(sb + (r * 136 + c4 * 4) * 4, g_Bf + (size_t)r * 512 + c4 * 4);
        }
        asm volatile("cp.async.commit_group;");
    }

    for (int nt = 0; nt < 4; nt++) {
        float acc[4][8][4];
#pragma unroll
        for (int i = 0; i < 4; i++)
#pragma unroll
            for (int j = 0; j < 8; j++)
#pragma unroll
                for (int q = 0; q < 4; q++) acc[i][j][q] = 0.f;

        for (int ch = 0; ch < 16; ch++) {
            const int ls = nt * 16 + ch;
            const int buf = ls & 1;
            __syncthreads();                    // prior stage fully consumed
            // --- gen A chunk: rows grow & grow+64, 16 k each ---
            {
                const bool iscos = (ch < 8);    // k0 = 32ch < 256
                float2 cur = bA0;
                const int rb = grow * 36 + 16 * gh;
#pragma unroll
                for (int q = 0; q < 16; q++) {
                    As[rb + q] = tf32u(iscos ? cur.x : cur.y);
                    cur = cmulf(cur, S1c0);
                }
                cur = bA1;
                const int rb1 = (grow + 64) * 36 + 16 * gh;
#pragma unroll
                for (int q = 0; q < 16; q++) {
                    As[rb1 + q] = tf32u(iscos ? cur.x : cur.y);
                    cur = cmulf(cur, S1c1);
                }
            }
            // --- prefetch next stage (B via cp.async into buf^1; A bases) ---
            {
                const int lsn = (ls + 1) & 63;
                const int ntn = lsn >> 4, chn = lsn & 15;
                const int k0n = 32 * chn;
                const uint32_t sb = su32(Bs) + (buf ^ 1) * 4352 * 4;
#pragma unroll
                for (int it = 0; it < 8; it++) {
                    int idx = it * 128 + tid, r = idx >> 5, c4 = idx & 31;
                    cp16(sb + (r * 136 + c4 * 4) * 4,
                         g_Bf + (size_t)(k0n + r) * 512 + ntn * 128 + c4 * 4);
                }
                asm volatile("cp.async.commit_group;");
                const int jn = ((2 * chn) & 15) + gh;
                bA0 = g_PCH[(size_t)(m0 + grow)      * 16 + jn];
                bA1 = g_PCH[(size_t)(m0 + grow + 64) * 16 + jn];
            }
            asm volatile("cp.async.wait_group 1;");
            __syncthreads();
            // --- MMA: warp 64x64 ---
            const uint32_t* Bp = Bs + buf * 4352;
#pragma unroll
            for (int ks = 0; ks < 4; ks++) {
                uint32_t af[4][4];
#pragma unroll
                for (int fm = 0; fm < 4; fm++) {
                    int r = wm * 64 + fm * 16 + (lane >> 2);
                    int cb = ks * 8 + (lane & 3);
                    af[fm][0] = As[r * 36 + cb];
                    af[fm][1] = As[(r + 8) * 36 + cb];
                    af[fm][2] = As[r * 36 + cb + 4];
                    af[fm][3] = As[(r + 8) * 36 + cb + 4];
                }
#pragma unroll
                for (int fn = 0; fn < 8; fn++) {
                    int br = ks * 8 + (lane & 3);
                    int bc = wn * 64 + fn * 8 + (lane >> 2);
                    uint32_t bf[2];
                    bf[0] = Bp[br * 136 + bc];
                    bf[1] = Bp[(br + 4) * 136 + bc];
#pragma unroll
                    for (int fm = 0; fm < 4; fm++) mma8(acc[fm][fn], af[fm], bf);
                }
            }
        }
        // --- fused Ey-weighted partial reduction for this nt ---
#pragma unroll
        for (int fm = 0; fm < 4; fm++)
#pragma unroll
        for (int cp = 0; cp < 2; cp++) {
            const int rl = wm * 64 + fm * 16 + cp * 8 + (lane >> 2);
            const int m = m0 + rl;
            const float2 S1c  = conjf(g_S1y[m]);
            const float2 S64c = conjf(g_S64y[m]);
            const float2 EYp  = g_S128y[m];
            const int a2 = ((nt & 1) << 1) | wn;
            float2 S2c = cmulf(S1c, S1c);
            float2 base = cmulf(cmulf(EYp, cpow4(S64c, a2)), cpow4(S2c, lane & 3));
            float2 S8c = cmulf(S2c, S2c); S8c = cmulf(S8c, S8c);
            float2 pb = base;
            float tx = 0.f, ty = 0.f;
#pragma unroll
            for (int fn = 0; fn < 8; fn++) {
                float v0 = acc[fm][fn][cp * 2 + 0];
                float v1 = acc[fm][fn][cp * 2 + 1];
                float2 p1 = cmulf(pb, S1c);
                if (nt < 2) { tx += v0 * pb.x + v1 * p1.x;  ty += v0 * pb.y + v1 * p1.y; }
                else        { tx -= v0 * pb.y + v1 * p1.y;  ty += v0 * pb.x + v1 * p1.x; }
                pb = cmulf(pb, S8c);
            }
            tx += __shfl_xor_sync(0xffffffffu, tx, 1);
            ty += __shfl_xor_sync(0xffffffffu, ty, 1);
            tx += __shfl_xor_sync(0xffffffffu, tx, 2);
            ty += __shfl_xor_sync(0xffffffffu, ty, 2);
            if ((lane & 3) == 0) {
                t_acc[wn * 128 + rl].x += tx;
                t_acc[wn * 128 + rl].y += ty;
            }
        }
    }
    __syncthreads();
    {
        const int m = m0 + tid;
        float2 t = make_float2(t_acc[tid].x + t_acc[128 + tid].x,
                               t_acc[tid].y + t_acc[128 + tid].y);
        const float lam = 1.0f / (1.0f + expf(-lamp[0]));
        const float kx = kxs[m], ky = kys[m];
        const float dcf = sqrtf(kx * kx + ky * ky);
        const int sp = m / 640, sam = m - sp * 640;
        const float2 y = yrad[sam * 288 + sp];
        const float w = lam * dcf * ORTHO;
        float2 kdc = make_float2(fmaf(w, t.x, (1.f - lam) * y.x),
                                 fmaf(w, t.y, (1.f - lam) * y.y));
        g_E0[m] = cmulf(kdc, conjf(g_S128y[m]));
    }
}

// ---------------------------------------------------------------------------
// Adjoint GEMM. CTA: 128 u x 128 n, 128 threads (4 warps 2x2), warp 64x64.
// grid (split 72, ut 2, nt 4). K-slice 2560 m, 160 stages of 16 m (K=32).
// A/B tiles generated per stage from prefetched per-m tables; no G in DRAM.
// ---------------------------------------------------------------------------
__global__ __launch_bounds__(128)
void adj_gemm()
{
    __shared__ uint32_t As[128 * 36];
    __shared__ uint32_t Bs[32 * 136];

    const int tid = threadIdx.x, lane = tid & 31, wid = tid >> 5;
    const int wm = wid >> 1, wn = wid & 1;
    const int split = blockIdx.x, ut = blockIdx.y, nt = blockIdx.z;
    const int mb = split * ADJ_MPER;
    const int gm = tid >> 3, sub = tid & 7;
    const bool isRe = (nt < 2);
    const int yb = nt & 1;

    float acc[4][8][4];
#pragma unroll
    for (int i = 0; i < 4; i++)
#pragma unroll
        for (int j = 0; j < 8; j++)
#pragma unroll
            for (int q = 0; q < 4; q++) acc[i][j][q] = 0.f;

    // prefetch stage-0 tables
    int mp = mb + gm;
    float2 tA  = g_PXU[(size_t)mp * 16 + ut * 8 + sub];
    float2 tSx = g_S8x[mp];
    float2 tE  = g_E0[mp];
    float2 tPy = g_PYB[(size_t)mp * 16 + yb * 8 + sub];
    float2 tSy = g_S8y[mp];

    for (int st = 0; st < ADJ_ST; st++) {
        __syncthreads();
        // --- gen A: e^{+i kx u'}, u = sub + 8q, u' = ut*128 + u - 128 ---
        {
            float2 cur = tA;
#pragma unroll
            for (int q = 0; q < 16; q++) {
                const int u = sub + 8 * q;
                As[u * 36 + 2 * gm]     = tf32u(cur.x);   // cos
                As[u * 36 + 2 * gm + 1] = tf32u(cur.y);   // sin
                cur = cmulf(cur, tSx);
            }
        }
        // --- gen B: G(v) = E0 * S1y^v (v incl. 128 offset via yb table) ---
        {
            float2 cur = cmulf(tE, tPy);
#pragma unroll
            for (int q = 0; q < 16; q++) {
                const int v = sub + 8 * q;
                if (isRe) {
                    Bs[(2 * gm)     * 136 + v] = tf32u(cur.x);
                    Bs[(2 * gm + 1) * 136 + v] = tf32u(-cur.y);
                } else {
                    Bs[(2 * gm)     * 136 + v] = tf32u(cur.y);
                    Bs[(2 * gm + 1) * 136 + v] = tf32u(cur.x);
                }
                cur = cmulf(cur, tSy);
            }
        }
        // --- prefetch next stage's tables (hides under MMA) ---
        if (st < ADJ_ST - 1) {
            mp = mb + (st + 1) * 16 + gm;
            tA  = g_PXU[(size_t)mp * 16 + ut * 8 + sub];
            tSx = g_S8x[mp];
            tE  = g_E0[mp];
            tPy = g_PYB[(size_t)mp * 16 + yb * 8 + sub];
            tSy = g_S8y[mp];
        }
        __syncthreads();
        // --- MMA: warp 64x64 ---
#pragma unroll
        for (int ks = 0; ks < 4; ks++) {
            uint32_t af[4][4];
#pragma unroll
            for (int fm = 0; fm < 4; fm++) {
                int r = wm * 64 + fm * 16 + (lane >> 2);
                int cb = ks * 8 + (lane & 3);
                af[fm][0] = As[r * 36 + cb];
                af[fm][1] = As[(r + 8) * 36 + cb];
                af[fm][2] = As[r * 36 + cb + 4];
                af[fm][3] = As[(r + 8) * 36 + cb + 4];
            }
#pragma unroll
            for (int fn = 0; fn < 8; fn++) {
                int br = ks * 8 + (lane & 3);
                int bc = wn * 64 + fn * 8 + (lane >> 2);
                uint32_t bf[2];
                bf[0] = Bs[br * 136 + bc];
                bf[1] = Bs[(br + 4) * 136 + bc];
#pragma unroll
                for (int fm = 0; fm < 4; fm++) mma8(acc[fm][fn], af[fm], bf);
            }
        }
    }

    float* outp = g_P + (size_t)((ut * 4 + nt) * NSPLIT + split) * 16384;
#pragma unroll
    for (int fm = 0; fm < 4; fm++)
#pragma unroll
    for (int cp = 0; cp < 2; cp++) {
        const int u = wm * 64 + fm * 16 + cp * 8 + (lane >> 2);
#pragma unroll
        for (int fn = 0; fn < 8; fn++) {
            const int n = wn * 64 + fn * 8 + 2 * (lane & 3);
            *(float2*)&outp[u * 128 + n] =
                make_float2(acc[fm][fn][cp * 2], acc[fm][fn][cp * 2 + 1]);
        }
    }
}

// ---------------------------------------------------------------------------
__global__ __launch_bounds__(256) void reduce_k(float* __restrict__ out)
{
    const int idx = blockIdx.x * 256 + threadIdx.x;     // 0..131071
    const int ug = idx >> 9, ng = idx & 511;
    const int ut = ug >> 7, ul = ug & 127, nt = ng >> 7, nl = ng & 127;
    const float* p = g_P + (size_t)((ut * 4 + nt) * NSPLIT) * 16384 + ul * 128 + nl;
    float s = 0.f;
#pragma unroll 8
    for (int sp = 0; sp < NSPLIT; sp++) s += p[(size_t)sp * 16384];
    const int v = ng & 255, c = ng >> 8;
    out[(ug * 256 + v) * 2 + c] = s * ORTHO;
}

// ---------------------------------------------------------------------------
extern "C" void kernel_launch(void* const* d_in, const int* in_sizes, int n_in,
                              void* d_out, int out_size)
{
    const float2* img  = (const float2*)d_in[0];
    const float2* yrad = (const float2*)d_in[1];
    const float*  lamp = (const float*)d_in[2];
    const float*  ktr  = (const float*)d_in[3];
    const float*  kxs  = ktr;
    const float*  kys  = ktr + MTOT;
    float* out = (float*)d_out;

    const int FWD_SMEM = (4608 + 8704 + 512) * 4;   // 55296 B
    cudaFuncSetAttribute(fwd_gemm, cudaFuncAttributeMaxDynamicSharedMemorySize, FWD_SMEM);

    prep_tab<<<MTOT/256, 256>>>(kxs, kys);
    prep_bf<<<1024, 256>>>(img);
    fwd_gemm<<<MTOT/128, 128, FWD_SMEM>>>(yrad, lamp, kxs, kys);
    adj_gemm<<<dim3(NSPLIT, 2, 4), 128>>>();
    reduce_k<<<512, 256>>>(out);
}